// round 4
// baseline (speedup 1.0000x reference)
#include <cuda_runtime.h>
#include <cuda_bf16.h>
#include <cstdint>

#define D      64
#define NROWS  8192
#define BM     128
#define BN     128
#define KS     128      // smem K extent: [hi(0..63) | lo(64..127)]
#define LDT    136      // smem row stride (bf16): 272B -> conflict-free LDSM
#define GAMMA  0.015625f
#define TWOG   0.03125f

// ---------------- device scratch (no allocation allowed) ----------------
__device__ float g_xs[NROWS];
__device__ float g_ys[NROWS];
__device__ __nv_bfloat16 g_A2[NROWS * KS];   // [row][ hi(64) | lo(64) ]
__device__ __nv_bfloat16 g_B2[NROWS * KS];

// ---------------- prep (merged): bf16 hi/lo split + (-gamma*||row||^2) ----
__global__ void __launch_bounds__(256)
prep_kernel(const float* __restrict__ A, const float* __restrict__ B,
            int rows_each) {
    int half = gridDim.x >> 1;
    int bid  = blockIdx.x;
    const float* X;
    __nv_bfloat16* dst;
    float* nrm;
    if (bid < half) { X = A; dst = g_A2; nrm = g_xs; }
    else            { X = B; dst = g_B2; nrm = g_ys; bid -= half; }

    int w    = bid * 8 + (threadIdx.x >> 5);
    int lane = threadIdx.x & 31;
    if (w >= rows_each) return;
    const float* r = X + (size_t)w * D;
    float f0 = r[lane];
    float f1 = r[lane + 32];

    __nv_bfloat16 h0 = __float2bfloat16_rn(f0);
    __nv_bfloat16 h1 = __float2bfloat16_rn(f1);
    size_t base = (size_t)w * KS;
    dst[base + lane]           = h0;
    dst[base + lane + 32]      = h1;
    dst[base + 64 + lane]      = __float2bfloat16_rn(f0 - __bfloat162float(h0));
    dst[base + 64 + lane + 32] = __float2bfloat16_rn(f1 - __bfloat162float(h1));

    float s = f0 * f0 + f1 * f1;
#pragma unroll
    for (int o = 16; o; o >>= 1) s += __shfl_xor_sync(0xffffffffu, s, o);
    if (lane == 0) nrm[w] = -GAMMA * s;
}

// ---------------- PTX helpers ----------------
__device__ __forceinline__ void mma16816(float* d, const uint32_t* a,
                                         const uint32_t* b) {
    asm volatile(
        "mma.sync.aligned.m16n8k16.row.col.f32.bf16.bf16.f32 "
        "{%0,%1,%2,%3}, {%4,%5,%6,%7}, {%8,%9}, {%0,%1,%2,%3};"
        : "+f"(d[0]), "+f"(d[1]), "+f"(d[2]), "+f"(d[3])
        : "r"(a[0]), "r"(a[1]), "r"(a[2]), "r"(a[3]), "r"(b[0]), "r"(b[1]));
}
__device__ __forceinline__ void ldsm_x4(uint32_t* r, uint32_t addr) {
    asm volatile("ldmatrix.sync.aligned.m8n8.x4.shared.b16 {%0,%1,%2,%3}, [%4];"
                 : "=r"(r[0]), "=r"(r[1]), "=r"(r[2]), "=r"(r[3]) : "r"(addr));
}
__device__ __forceinline__ void ldsm_x2(uint32_t* r, uint32_t addr) {
    asm volatile("ldmatrix.sync.aligned.m8n8.x2.shared.b16 {%0,%1}, [%2];"
                 : "=r"(r[0]), "=r"(r[1]) : "r"(addr));
}
__device__ __forceinline__ uint32_t smem_u32(const void* p) {
    uint32_t a;
    asm("{ .reg .u64 t; cvta.to.shared.u64 t, %1; cvt.u32.u64 %0, t; }"
        : "=r"(a) : "l"(p));
    return a;
}

// ---------------- main: store-interleaved split-bf16 HMMA ----------------
extern __shared__ __nv_bfloat16 smem[];

__global__ void __launch_bounds__(256, 3)
rbf_mma_kernel(float* __restrict__ out, int N) {
    __nv_bfloat16* As = smem;                 // [128][LDT]
    __nv_bfloat16* Bs = smem + BM * LDT;      // [128][LDT]

    const int tid  = threadIdx.x;
    const int lane = tid & 31;
    const int wid  = tid >> 5;
    const int gID  = lane >> 2;   // 0..7
    const int tig  = lane & 3;    // 0..3
    const int wm   = wid >> 2;    // 0..1 : 64-row slab
    const int wn   = wid & 3;     // 0..3 : 32-col slab
    const int row0 = blockIdx.y * BM;
    const int col0 = blockIdx.x * BN;

    // ---- load tiles (128 rows x 128 bf16 each) into padded smem ----
    {
        const uint4* ga = reinterpret_cast<const uint4*>(g_A2 + (size_t)row0 * KS);
        const uint4* gb = reinterpret_cast<const uint4*>(g_B2 + (size_t)col0 * KS);
#pragma unroll
        for (int t = 0; t < 8; t++) {
            int id = t * 256 + tid;     // 0..2047
            int r  = id >> 4;           // 0..127
            int q  = id & 15;           // 16B chunk
            *reinterpret_cast<uint4*>(As + r * LDT + q * 8) = ga[r * 16 + q];
            *reinterpret_cast<uint4*>(Bs + r * LDT + q * 8) = gb[r * 16 + q];
        }
    }
    __syncthreads();

    // ---- per-lane ldmatrix base addresses ----
    const int quad = lane >> 3;        // 0..3
    const int lr   = lane & 7;         // 0..7
    // A: matrix quad -> (row += (quad&1)*8, k += (quad>>1)*8)
    const uint32_t aBase = smem_u32(As) +
        (uint32_t)(((wm * 64 + (quad & 1) * 8 + lr) * LDT + (quad >> 1) * 8) * 2);
    // B x2: half = (lane>>3)&1 -> k += half*8 (lanes 16-31 mirror, ignored)
    const uint32_t bBase = smem_u32(Bs) +
        (uint32_t)(((wn * 32 + lr) * LDT + (quad & 1) * 8) * 2);

    // ---- mt-outer loop: 12 MMAs per (mt,nt) chunk, store immediately ----
#pragma unroll
    for (int mt = 0; mt < 4; mt++) {
        uint32_t ahi[4][4], alo[4][4];
#pragma unroll
        for (int ks = 0; ks < 4; ks++) {
            ldsm_x4(ahi[ks], aBase + (uint32_t)((mt * 16 * LDT + ks * 16) * 2));
            ldsm_x4(alo[ks], aBase + (uint32_t)((mt * 16 * LDT + ks * 16 + 64) * 2));
        }
        const int rbase = row0 + wm * 64 + mt * 16 + gID;
        const float xs0 = g_xs[rbase];
        const float xs1 = g_xs[rbase + 8];

#pragma unroll
        for (int nt = 0; nt < 4; nt++) {
            float acc[4] = {0.f, 0.f, 0.f, 0.f};
#pragma unroll
            for (int ks = 0; ks < 4; ks++) {
                uint32_t bhi[2], blo[2];
                ldsm_x2(bhi, bBase + (uint32_t)((nt * 8 * LDT + ks * 16) * 2));
                ldsm_x2(blo, bBase + (uint32_t)((nt * 8 * LDT + ks * 16 + 64) * 2));
                mma16816(acc, ahi[ks], bhi);
                mma16816(acc, ahi[ks], blo);
                mma16816(acc, alo[ks], bhi);
            }
            const int c = col0 + wn * 32 + nt * 8 + 2 * tig;
            const float2 ysv = *reinterpret_cast<const float2*>(&g_ys[c]);
            float2 v0, v1;
            v0.x = __expf(fminf(xs0 + ysv.x + TWOG * acc[0], 0.f));
            v0.y = __expf(fminf(xs0 + ysv.y + TWOG * acc[1], 0.f));
            v1.x = __expf(fminf(xs1 + ysv.x + TWOG * acc[2], 0.f));
            v1.y = __expf(fminf(xs1 + ysv.y + TWOG * acc[3], 0.f));
            *reinterpret_cast<float2*>(out + (size_t)rbase * N + c)       = v0;
            *reinterpret_cast<float2*>(out + (size_t)(rbase + 8) * N + c) = v1;
        }
    }
}

// ---------------------------------------------------------------------------
extern "C" void kernel_launch(void* const* d_in, const int* in_sizes, int n_in,
                              void* d_out, int out_size) {
    const float* A = (const float*)d_in[0];  // data        [M, 64]
    const float* B = (const float*)d_in[1];  // support_vec [N, 64]
    float* out     = (float*)d_out;          // [M, N]

    const int M = in_sizes[0] / D;           // 8192
    const int N = in_sizes[1] / D;           // 8192

    prep_kernel<<<(M + 7) / 8 * 2, 256>>>(A, B, M);

    const int smem_bytes = 2 * BM * LDT * sizeof(__nv_bfloat16);  // 69632
    cudaFuncSetAttribute(rbf_mma_kernel,
                         cudaFuncAttributeMaxDynamicSharedMemorySize, smem_bytes);
    dim3 grid(N / BN, M / BM);
    rbf_mma_kernel<<<grid, 256, smem_bytes>>>(out, N);
}

// round 5
// speedup vs baseline: 1.3644x; 1.3644x over previous
#include <cuda_runtime.h>
#include <cstdint>

#define D      64
#define NROWS  8192
#define BM     128
#define BN     128
#define LDTF   68       // smem row stride in floats (272B): bank = (4r + c) % 32
#define GAMMA  0.015625f
#define TWOG   0.03125f

// ---------------- device scratch (no allocation allowed) ----------------
__device__ float g_xs[NROWS];
__device__ float g_ys[NROWS];
__device__ float g_At[NROWS * D];   // tf32-rounded data
__device__ float g_Bt[NROWS * D];   // tf32-rounded support vectors

// ---------------- prep: tf32 round + (-gamma * ||row||^2) ----------------
__global__ void __launch_bounds__(256)
prep_kernel(const float* __restrict__ A, const float* __restrict__ B,
            int rows_each) {
    int half = gridDim.x >> 1;
    int bid  = blockIdx.x;
    const float* X;
    float* dst;
    float* nrm;
    if (bid < half) { X = A; dst = g_At; nrm = g_xs; }
    else            { X = B; dst = g_Bt; nrm = g_ys; bid -= half; }

    int w    = bid * 8 + (threadIdx.x >> 5);
    int lane = threadIdx.x & 31;
    if (w >= rows_each) return;
    const float* r = X + (size_t)w * D;
    float f0 = r[lane];
    float f1 = r[lane + 32];

    uint32_t t0, t1;
    asm("cvt.rna.tf32.f32 %0, %1;" : "=r"(t0) : "f"(f0));
    asm("cvt.rna.tf32.f32 %0, %1;" : "=r"(t1) : "f"(f1));
    dst[(size_t)w * D + lane]      = __uint_as_float(t0);
    dst[(size_t)w * D + lane + 32] = __uint_as_float(t1);

    float s = f0 * f0 + f1 * f1;   // norms from exact f32
#pragma unroll
    for (int o = 16; o; o >>= 1) s += __shfl_xor_sync(0xffffffffu, s, o);
    if (lane == 0) nrm[w] = -GAMMA * s;
}

// ---------------- tf32 mma helper ----------------
__device__ __forceinline__ void mma_tf32(float* d, const uint32_t* a,
                                         const uint32_t* b) {
    asm volatile(
        "mma.sync.aligned.m16n8k8.row.col.f32.tf32.tf32.f32 "
        "{%0,%1,%2,%3}, {%4,%5,%6,%7}, {%8,%9}, {%0,%1,%2,%3};"
        : "+f"(d[0]), "+f"(d[1]), "+f"(d[2]), "+f"(d[3])
        : "r"(a[0]), "r"(a[1]), "r"(a[2]), "r"(a[3]), "r"(b[0]), "r"(b[1]));
}

// store-coalescing permutation within each 16-row group of the B tile:
// smem pos p holds gmem sv (group + perm(p)) so each thread's outputs across
// an nt-pair land on 4 consecutive gmem columns (float4 store).
__device__ __forceinline__ int perm16(int p) {
    return (p < 8) ? ((p >> 1) * 4 + (p & 1))
                   : (((p - 8) >> 1) * 4 + (p & 1) + 2);
}

// ---------------- main: tf32 HMMA, hoisted B frags, STG.128 epilogue ------
extern __shared__ float smemf[];

__global__ void __launch_bounds__(256, 2)
rbf_tf32_kernel(float* __restrict__ out, int N) {
    float* As = smemf;               // [128][LDTF]  row = m, col = k
    float* Bs = smemf + BM * LDTF;   // [128][LDTF]  row = n (permuted), col = k

    const int tid  = threadIdx.x;
    const int lane = tid & 31;
    const int wid  = tid >> 5;
    const int gID  = lane >> 2;   // 0..7
    const int tig  = lane & 3;    // 0..3
    const int wm   = wid >> 2;    // 0..1 : 64-row slab
    const int wn   = wid & 3;     // 0..3 : 32-col slab
    const int row0 = blockIdx.y * BM;
    const int col0 = blockIdx.x * BN;

    // ---- load tiles (128 x 64 f32 each); B rows permuted per 16-group ----
    {
        const float4* ga = reinterpret_cast<const float4*>(g_At);
        const float4* gb = reinterpret_cast<const float4*>(g_Bt);
#pragma unroll
        for (int t = 0; t < 8; t++) {
            int id = t * 256 + tid;     // 0..2047
            int r  = id >> 4;           // 0..127
            int q  = id & 15;           // float4 chunk 0..15
            float4 va = ga[(size_t)(row0 + r) * 16 + q];
            *reinterpret_cast<float4*>(As + r * LDTF + q * 4) = va;
            int src = col0 + (r & ~15) + perm16(r & 15);
            float4 vb = gb[(size_t)src * 16 + q];
            *reinterpret_cast<float4*>(Bs + r * LDTF + q * 4) = vb;
        }
    }
    __syncthreads();

    // ---- hoist ALL B fragments for this warp's 32-col slab (64 regs) ----
    uint32_t bf[4][8][2];
    {
        const float* bb = Bs + (wn * 32 + gID) * LDTF + tig;
#pragma unroll
        for (int nt = 0; nt < 4; nt++)
#pragma unroll
            for (int ks = 0; ks < 8; ks++) {
                const float* p = bb + nt * 8 * LDTF + ks * 8;
                bf[nt][ks][0] = __float_as_uint(p[0]);
                bf[nt][ks][1] = __float_as_uint(p[4]);
            }
    }

    const float* ab = As + (wm * 64 + gID) * LDTF + tig;

#pragma unroll
    for (int mt = 0; mt < 4; mt++) {
        // A fragments for this 16-row tile (32 regs)
        uint32_t af[8][4];
#pragma unroll
        for (int ks = 0; ks < 8; ks++) {
            const float* p = ab + mt * 16 * LDTF + ks * 8;
            af[ks][0] = __float_as_uint(p[0]);
            af[ks][1] = __float_as_uint(p[8 * LDTF]);
            af[ks][2] = __float_as_uint(p[4]);
            af[ks][3] = __float_as_uint(p[8 * LDTF + 4]);
        }
        const int rbase = row0 + wm * 64 + mt * 16 + gID;
        const float xs0 = g_xs[rbase];
        const float xs1 = g_xs[rbase + 8];

#pragma unroll
        for (int pr = 0; pr < 2; pr++) {
            float accE[4] = {0.f, 0.f, 0.f, 0.f};
            float accO[4] = {0.f, 0.f, 0.f, 0.f};
#pragma unroll
            for (int ks = 0; ks < 8; ks++) {
                mma_tf32(accE, af[ks], bf[2 * pr][ks]);
                mma_tf32(accO, af[ks], bf[2 * pr + 1][ks]);
            }
            // gmem cols: 4 consecutive at c (thanks to B-row permutation)
            const int c = col0 + wn * 32 + pr * 16 + 4 * tig;
            const float4 ys4 = *reinterpret_cast<const float4*>(&g_ys[c]);
            float4 v0, v1;
            v0.x = __expf(fminf(xs0 + ys4.x + TWOG * accE[0], 0.f));
            v0.y = __expf(fminf(xs0 + ys4.y + TWOG * accE[1], 0.f));
            v0.z = __expf(fminf(xs0 + ys4.z + TWOG * accO[0], 0.f));
            v0.w = __expf(fminf(xs0 + ys4.w + TWOG * accO[1], 0.f));
            v1.x = __expf(fminf(xs1 + ys4.x + TWOG * accE[2], 0.f));
            v1.y = __expf(fminf(xs1 + ys4.y + TWOG * accE[3], 0.f));
            v1.z = __expf(fminf(xs1 + ys4.z + TWOG * accO[2], 0.f));
            v1.w = __expf(fminf(xs1 + ys4.w + TWOG * accO[3], 0.f));
            *reinterpret_cast<float4*>(out + (size_t)rbase * N + c)       = v0;
            *reinterpret_cast<float4*>(out + (size_t)(rbase + 8) * N + c) = v1;
        }
    }
}

// ---------------------------------------------------------------------------
extern "C" void kernel_launch(void* const* d_in, const int* in_sizes, int n_in,
                              void* d_out, int out_size) {
    const float* A = (const float*)d_in[0];  // data        [M, 64]
    const float* B = (const float*)d_in[1];  // support_vec [N, 64]
    float* out     = (float*)d_out;          // [M, N]

    const int M = in_sizes[0] / D;           // 8192
    const int N = in_sizes[1] / D;           // 8192

    prep_kernel<<<(M + 7) / 8 * 2, 256>>>(A, B, M);

    const int smem_bytes = 2 * BM * LDTF * sizeof(float);  // 69632
    cudaFuncSetAttribute(rbf_tf32_kernel,
                         cudaFuncAttributeMaxDynamicSharedMemorySize, smem_bytes);
    dim3 grid(N / BN, M / BM);
    rbf_tf32_kernel<<<grid, 256, smem_bytes>>>(out, N);
}

// round 6
// speedup vs baseline: 1.6498x; 1.2092x over previous
#include <cuda_runtime.h>
#include <cstdint>

#define D      64
#define NROWS  8192
#define BM     128
#define BN     128
#define GAMMA  0.015625f
#define TWOG   0.03125f

// ---------------- device scratch: fragment-layout tf32 inputs ----------------
// A: g_Af[group(r>>4)][chunk(k>>3)][lane((r&7)*4+(k&3))][word(((k>>2)&1)*2+((r>>3)&1))]
// B: g_Bf[group][chunk(k>>4)][lane(gID*4+(k&3))][word((k>>2)&3)]   (col-permuted)
__device__ float g_xs[NROWS];
__device__ float g_ys[NROWS];
__device__ float g_Af[NROWS * D];
__device__ float g_Bf[NROWS * D];

// ---------------- prep: tf32 round + fragment scatter + norms ----------------
__device__ __forceinline__ uint32_t tf32_of(float f) {
    uint32_t t;
    asm("cvt.rna.tf32.f32 %0, %1;" : "=r"(t) : "f"(f));
    return t;
}
__device__ __forceinline__ int idxA(int r, int k) {
    int grp  = r >> 4;
    int chnk = k >> 3;
    int lane = (r & 7) * 4 + (k & 3);
    int word = ((k >> 2) & 1) * 2 + ((r >> 3) & 1);
    return ((grp * 8 + chnk) * 32 + lane) * 4 + word;
}
__device__ __forceinline__ int idxB(int j, int k) {
    int w   = j & 15;                                   // within 16-col block
    int p   = 2 * (w >> 2) + (w & 1) + 8 * ((w >> 1) & 1);  // inverse perm16
    int grp = (j >> 4) * 2 + (p >> 3);
    int gID = p & 7;
    int lane = gID * 4 + (k & 3);
    int chnk = (k >> 4) & 3;
    int word = (k >> 2) & 3;
    return ((grp * 4 + chnk) * 32 + lane) * 4 + word;
}

__global__ void __launch_bounds__(256)
prep_kernel(const float* __restrict__ A, const float* __restrict__ B,
            int rows_each) {
    int half = gridDim.x >> 1;
    int bid  = blockIdx.x;
    bool isB = bid >= half;
    if (isB) bid -= half;

    int w    = bid * 8 + (threadIdx.x >> 5);
    int lane = threadIdx.x & 31;
    if (w >= rows_each) return;
    const float* r = (isB ? B : A) + (size_t)w * D;
    float f0 = r[lane];
    float f1 = r[lane + 32];

    if (!isB) {
        g_Af[idxA(w, lane)]      = __uint_as_float(tf32_of(f0));
        g_Af[idxA(w, lane + 32)] = __uint_as_float(tf32_of(f1));
    } else {
        g_Bf[idxB(w, lane)]      = __uint_as_float(tf32_of(f0));
        g_Bf[idxB(w, lane + 32)] = __uint_as_float(tf32_of(f1));
    }

    float s = f0 * f0 + f1 * f1;   // norms from exact f32
#pragma unroll
    for (int o = 16; o; o >>= 1) s += __shfl_xor_sync(0xffffffffu, s, o);
    if (lane == 0) (isB ? g_ys : g_xs)[w] = -GAMMA * s;
}

// ---------------- tf32 mma helper ----------------
__device__ __forceinline__ void mma_tf32(float* d, const uint32_t* a,
                                         const uint32_t* b) {
    asm volatile(
        "mma.sync.aligned.m16n8k8.row.col.f32.tf32.tf32.f32 "
        "{%0,%1,%2,%3}, {%4,%5,%6,%7}, {%8,%9}, {%0,%1,%2,%3};"
        : "+f"(d[0]), "+f"(d[1]), "+f"(d[2]), "+f"(d[3])
        : "r"(a[0]), "r"(a[1]), "r"(a[2]), "r"(a[3]), "r"(b[0]), "r"(b[1]));
}

// ---------------- main: smem-free tf32 HMMA, direct fragment LDG ----------
__global__ void __launch_bounds__(256, 2)
rbf_tf32_kernel(float* __restrict__ out, int N) {
    const int tid  = threadIdx.x;
    const int lane = tid & 31;
    const int wid  = tid >> 5;
    const int gID  = lane >> 2;
    const int tig  = lane & 3;
    const int wm   = wid >> 2;    // 0..1 : 64-row slab
    const int wn   = wid & 3;     // 0..3 : 32-col slab
    const int row0 = blockIdx.y * BM;
    const int col0 = blockIdx.x * BN;

    const uint4* Af = reinterpret_cast<const uint4*>(g_Af);
    const uint4* Bf = reinterpret_cast<const uint4*>(g_Bf);

    // ---- hoist ALL B fragments for this warp's 32-col slab (16 LDG.128) ----
    uint4 bf[16];   // [nt][chunk]
    {
        const int bgrp0 = (col0 >> 3) + wn * 4;
#pragma unroll
        for (int nt = 0; nt < 4; nt++)
#pragma unroll
            for (int c = 0; c < 4; c++)
                bf[nt * 4 + c] = Af == Bf ? bf[0]  // never taken; keep compiler calm
                    : Bf[(size_t)(((bgrp0 + nt) * 4 + c) * 32 + lane)];
    }
    const uint32_t* bw = reinterpret_cast<const uint32_t*>(bf);

#pragma unroll
    for (int mt = 0; mt < 4; mt++) {
        // A fragments for this 16-row group (8 LDG.128)
        uint4 af[8];
        const int agrp = (row0 >> 4) + wm * 4 + mt;
#pragma unroll
        for (int c = 0; c < 8; c++)
            af[c] = Af[(size_t)((agrp * 8 + c) * 32 + lane)];
        const uint32_t* aw = reinterpret_cast<const uint32_t*>(af);

        const int rbase = row0 + wm * 64 + mt * 16 + gID;
        const float xs0 = g_xs[rbase];
        const float xs1 = g_xs[rbase + 8];

#pragma unroll
        for (int pr = 0; pr < 2; pr++) {
            float accE[4] = {0.f, 0.f, 0.f, 0.f};
            float accO[4] = {0.f, 0.f, 0.f, 0.f};
#pragma unroll
            for (int ks = 0; ks < 8; ks++) {
                const uint32_t* a = aw + ks * 4;
                const uint32_t* bE =
                    bw + ((2 * pr) * 4 + (ks >> 1)) * 4 + (ks & 1) * 2;
                const uint32_t* bO =
                    bw + ((2 * pr + 1) * 4 + (ks >> 1)) * 4 + (ks & 1) * 2;
                mma_tf32(accE, a, bE);
                mma_tf32(accO, a, bO);
            }
            const int c = col0 + wn * 32 + pr * 16 + 4 * tig;
            const float4 ys4 = *reinterpret_cast<const float4*>(&g_ys[c]);
            float4 v0, v1;
            v0.x = __expf(fminf(xs0 + ys4.x + TWOG * accE[0], 0.f));
            v0.y = __expf(fminf(xs0 + ys4.y + TWOG * accE[1], 0.f));
            v0.z = __expf(fminf(xs0 + ys4.z + TWOG * accO[0], 0.f));
            v0.w = __expf(fminf(xs0 + ys4.w + TWOG * accO[1], 0.f));
            v1.x = __expf(fminf(xs1 + ys4.x + TWOG * accE[2], 0.f));
            v1.y = __expf(fminf(xs1 + ys4.y + TWOG * accE[3], 0.f));
            v1.z = __expf(fminf(xs1 + ys4.z + TWOG * accO[2], 0.f));
            v1.w = __expf(fminf(xs1 + ys4.w + TWOG * accO[3], 0.f));
            __stcs(reinterpret_cast<float4*>(out + (size_t)rbase * N + c), v0);
            __stcs(reinterpret_cast<float4*>(out + (size_t)(rbase + 8) * N + c), v1);
        }
    }
}

// ---------------------------------------------------------------------------
extern "C" void kernel_launch(void* const* d_in, const int* in_sizes, int n_in,
                              void* d_out, int out_size) {
    const float* A = (const float*)d_in[0];  // data        [M, 64]
    const float* B = (const float*)d_in[1];  // support_vec [N, 64]
    float* out     = (float*)d_out;          // [M, N]

    const int M = in_sizes[0] / D;           // 8192
    const int N = in_sizes[1] / D;           // 8192

    prep_kernel<<<(M + 7) / 8 * 2, 256>>>(A, B, M);

    dim3 grid(N / BN, M / BM);
    rbf_tf32_kernel<<<grid, 256>>>(out, N);
}